// round 13
// baseline (speedup 1.0000x reference)
#include <cuda_runtime.h>
#include <cuda_bf16.h>

// Problem constants (fixed by reference setup_inputs)
#define BATCH 2
#define C_    256
#define H_    200
#define W_    272
#define HW_   (H_*W_)
#define NROI  256
#define PH    15
#define PW    15
#define SXG   30
#define SYG   30
#define OH    14
#define OW    14
#define SCALE_ 0.25f

#define FULLMASK 0xFFFFFFFFu

struct XEnt { int jlo; int jhi; float w0; float w1; };       // relative to x0q
struct alignas(16) RW { int r[4]; float w[4]; };             // folded distinct rows per k

__device__ XEnt g_x[NROI][32];
__device__ RW   g_rw[NROI][PH];
__device__ int4 g_hdr[NROI];       // {x0q, boff, xs4, 0}
__device__ int  g_rows[NROI];      // max distinct rows over k (2..4)
__device__ int  g_perm[NROI];      // cost-descending roi order

// ---------------- Kernel A: per-roi tables ----------------
__global__ void roi_tab_kernel(const float* __restrict__ rois) {
    int n = blockIdx.x;
    int t = threadIdx.x;   // 64 threads

    float x1 = rois[n*5+1] * SCALE_;
    float y1 = rois[n*5+2] * SCALE_;
    float x2 = rois[n*5+3] * SCALE_;
    float y2 = rois[n*5+4] * SCALE_;
    float cx = 0.5f*(x1+x2), cy = 0.5f*(y1+y2);
    float hw = 0.5f*(x2-x1), hh = 0.5f*(y2-y1);
    x1 = cx - hw; x2 = cx + hw;
    y1 = cy - hh; y2 = cy + hh;
    float roi_w = fmaxf(x2 - x1, 1.0f);
    float roi_h = fmaxf(y2 - y1, 1.0f);
    float bw = roi_w / (float)PW;
    float bh = roi_h / (float)PH;

    if (t < 32) {
        int i = t;
        float sx = x1 + ((float)i + 0.5f) * (bw * 0.5f);
        bool valid = (sx > -1.0f) && (sx < (float)W_);
        float c = fminf(fmaxf(sx, 0.0f), (float)(W_-1));
        float lo = floorf(c);
        int ilo = (int)lo;
        int ihi = min(ilo + 1, W_-1);
        float fr = c - lo;
        float v = valid ? 1.0f : 0.0f;

        int x0q = __shfl_sync(FULLMASK, ilo, 0) & ~3;   // 16B-aligned span start
        int jhi29 = __shfl_sync(FULLMASK, ihi, 29) - x0q;

        XEnt e;
        if (i < SXG) { e.jlo = ilo - x0q; e.jhi = ihi - x0q; e.w0 = v*(1.0f-fr); e.w1 = v*fr; }
        else         { e.jlo = 0; e.jhi = 0; e.w0 = 0.0f; e.w1 = 0.0f; }
        g_x[n][i] = e;

        if (i == 0) {
            int xs4 = jhi29 >> 2;                  // last float4 word needed
            int boff = (int)rois[n*5+0] * (C_ * HW_);
            g_hdr[n] = make_int4(x0q, boff, xs4, 0);
        }
    } else if (t < 48) {
        int k = t - 32;
        int cnt = 2;
        if (k < PH) {
            int rr[4]; float ww[4]; int m = 0;

            #pragma unroll
            for (int j = 0; j < 2; j++) {
                int iy = 2*k + j;
                float sy = y1 + ((float)iy + 0.5f) * (bh * 0.5f);
                bool valid = (sy > -1.0f) && (sy < (float)H_);
                float c = fminf(fmaxf(sy, 0.0f), (float)(H_-1));
                float lo = floorf(c);
                int ilo = (int)lo;
                int ihi = min(ilo + 1, H_-1);
                float fr = c - lo;
                float v = valid ? 1.0f : 0.0f;
                float w0 = v*(1.0f-fr), w1 = v*fr;
                int r0 = ilo * W_, r1 = ihi * W_;

                if (w0 != 0.0f) {
                    bool done = false;
                    for (int q = 0; q < m; q++) if (rr[q] == r0) { ww[q] += w0; done = true; break; }
                    if (!done) { rr[m] = r0; ww[m] = w0; m++; }
                }
                if (w1 != 0.0f) {
                    bool done = false;
                    for (int q = 0; q < m; q++) if (rr[q] == r1) { ww[q] += w1; done = true; break; }
                    if (!done) { rr[m] = r1; ww[m] = w1; m++; }
                }
            }
            if (m == 0) { rr[0] = 0; ww[0] = 0.0f; m = 1; }
            cnt = max(m, 2);
            for (int q = m; q < 4; q++) { rr[q] = rr[0]; ww[q] = 0.0f; }

            RW rw;
            #pragma unroll
            for (int q = 0; q < 4; q++) { rw.r[q] = rr[q]; rw.w[q] = ww[q]; }
            g_rw[n][k] = rw;
        }
        int mx = cnt;
        #pragma unroll
        for (int d = 8; d >= 1; d >>= 1)
            mx = max(mx, __shfl_xor_sync(0xFFFFu, mx, d));
        if (k == 0) g_rows[n] = mx;
    }
}

// ---------------- Kernel A2: cost-descending bitonic sort of rois ----------------
__global__ void roi_sort_kernel() {
    __shared__ unsigned skey[NROI];
    int t = threadIdx.x;

    int4 hdr = g_hdr[t];
    int rows = g_rows[t];
    unsigned key = ((unsigned)rows << 16) | (((unsigned)hdr.z & 0xFF) << 8) | (unsigned)t;
    skey[t] = key;
    __syncthreads();

    for (int k = 2; k <= NROI; k <<= 1) {
        for (int j = k >> 1; j > 0; j >>= 1) {
            int ixj = t ^ j;
            if (ixj > t) {
                unsigned a = skey[t], b = skey[ixj];
                bool seg = ((t & k) == 0);
                if (seg ? (a < b) : (a > b)) { skey[t] = b; skey[ixj] = a; }
            }
            __syncthreads();
        }
    }
    g_perm[t] = (int)(skey[t] & 0xFFu);
}

// ---------------- Kernel B ----------------

// Gather the two x-taps from a float4-per-lane accumulated span.
__device__ __forceinline__ float gath4(float4 P,
                                       int le4, int lo4, int esel, int osel,
                                       int c0, int c1, float wx0, float wx1)
{
    float a0 = __shfl_sync(FULLMASK, P.x, le4);
    float a1 = __shfl_sync(FULLMASK, P.z, le4);
    float ex = esel ? a1 : a0;
    float b0 = __shfl_sync(FULLMASK, P.y, lo4);
    float b1 = __shfl_sync(FULLMASK, P.w, lo4);
    float oy = osel ? b1 : b0;
    float g0 = c0 ? oy : ex;
    float g1 = c1 ? oy : ex;
    return wx0*g0 + wx1*g1;
}

template<int ROWS>
__device__ __forceinline__ void pair_proc(
    const float* __restrict__ pu, const float* __restrict__ pv,
    const RW* __restrict__ srw,
    int lane, int xs4, int le4, int lo4, int esel, int osel,
    int c0, int c1, float wx0, float wx1,
    float* __restrict__ ou, float* __restrict__ ov)
{
    bool emit = ((lane & 1) == 0) && (lane < 28);
    int lofs = lane >> 1;

    int j0 = min(lane, xs4);

    float sPu = 0.0f, sPv = 0.0f;

    #pragma unroll 2
    for (int k = 0; k < 15; k++) {
        RW rw = srw[k];

        float4 au[ROWS], bv[ROWS];
        #pragma unroll
        for (int q = 0; q < ROWS; q++) {
            au[q] = __ldg((const float4*)(pu + rw.r[q]) + j0);
            bv[q] = __ldg((const float4*)(pv + rw.r[q]) + j0);
        }

        float4 Pu = make_float4(0.f,0.f,0.f,0.f);
        float4 Pv = make_float4(0.f,0.f,0.f,0.f);
        #pragma unroll
        for (int q = 0; q < ROWS; q++) {
            float w = rw.w[q];
            Pu.x += w*au[q].x; Pu.y += w*au[q].y; Pu.z += w*au[q].z; Pu.w += w*au[q].w;
            Pv.x += w*bv[q].x; Pv.y += w*bv[q].y; Pv.z += w*bv[q].z; Pv.w += w*bv[q].w;
        }

        float su = gath4(Pu, le4, lo4, esel, osel, c0, c1, wx0, wx1);
        float sv = gath4(Pv, le4, lo4, esel, osel, c0, c1, wx0, wx1);

        if (k) {
            float eu = sPu + su;
            float ev = sPv + sv;
            float tu = eu + __shfl_down_sync(FULLMASK, eu, 1);
            tu += __shfl_down_sync(FULLMASK, tu, 2);
            float tv = ev + __shfl_down_sync(FULLMASK, ev, 1);
            tv += __shfl_down_sync(FULLMASK, tv, 2);
            if (emit) {
                int idx = (k - 1) * OW + lofs;
                ou[idx] = tu * (1.0f/16.0f);
                ov[idx] = tv * (1.0f/16.0f);
            }
        }
        sPu = su;
        sPv = sv;
    }
}

__global__ __launch_bounds__(256, 7)
void roi_align_kernel(const float* __restrict__ feat, float* __restrict__ out) {
    __shared__ RW srw[PH];

    int n  = g_perm[blockIdx.x];
    int cg = blockIdx.y;          // 0..15, 16 channels per block
    int tid = threadIdx.x;
    int wid = tid >> 5, lane = tid & 31;

    if (tid < 2 * PH) {
        ((int4*)srw)[tid] = ((const int4*)g_rw[n])[tid];
    }
    __syncthreads();

    int4 hdr = g_hdr[n];
    int x0q = hdr.x, boff = hdr.y, xs4 = hdr.z;
    int rows = g_rows[n];

    XEnt xe = g_x[n][lane];
    int c0 = xe.jlo & 1;
    int c1 = xe.jhi & 1;
    int je = c0 ? xe.jhi : xe.jlo;   // even-column tap (when one exists)
    int jo = c0 ? xe.jlo : xe.jhi;   // odd-column tap (when one exists)
    int le4 = je >> 2, esel = (je >> 1) & 1;
    int lo4 = jo >> 2, osel = (jo >> 1) & 1;
    float wx0 = xe.w0, wx1 = xe.w1;

    int c = cg * 16 + wid * 2;       // each warp: one channel pair
    const float* pu = feat + boff + x0q + c * HW_;
    const float* pv = pu + HW_;
    float* ou = out + (size_t)(n * C_ + c) * (OH * OW);
    float* ov = ou + OH * OW;

    if (rows == 2)
        pair_proc<2>(pu, pv, srw, lane, xs4, le4, lo4, esel, osel, c0, c1, wx0, wx1, ou, ov);
    else if (rows == 3)
        pair_proc<3>(pu, pv, srw, lane, xs4, le4, lo4, esel, osel, c0, c1, wx0, wx1, ou, ov);
    else
        pair_proc<4>(pu, pv, srw, lane, xs4, le4, lo4, esel, osel, c0, c1, wx0, wx1, ou, ov);
}

extern "C" void kernel_launch(void* const* d_in, const int* in_sizes, int n_in,
                              void* d_out, int out_size) {
    const float* feat = (const float*)d_in[0];
    const float* rois = (const float*)d_in[1];
    float* out = (float*)d_out;

    roi_tab_kernel<<<NROI, 64>>>(rois);
    roi_sort_kernel<<<1, NROI>>>();
    dim3 grid(NROI, 16);
    roi_align_kernel<<<grid, 256>>>(feat, out);
}

// round 14
// speedup vs baseline: 1.0602x; 1.0602x over previous
#include <cuda_runtime.h>
#include <cuda_bf16.h>

// Problem constants (fixed by reference setup_inputs)
#define BATCH 2
#define C_    256
#define H_    200
#define W_    272
#define HW_   (H_*W_)
#define NROI  256
#define PH    15
#define PW    15
#define SXG   30
#define SYG   30
#define OH    14
#define OW    14
#define SCALE_ 0.25f

#define FULLMASK 0xFFFFFFFFu

struct XEnt { int jlo; int jhi; float w0; float w1; };       // relative to x0e, w pre-scaled by 1/16
struct alignas(16) RW { int r[4]; float w[4]; };             // folded distinct rows per k

__device__ XEnt g_x[NROI][32];
__device__ RW   g_rw[NROI][PH];
__device__ int4 g_hdr[NROI];       // {x0e, nw2, boff, span2-1}
__device__ int  g_rows[NROI];      // max distinct rows over k (2..4)
__device__ int  g_perm[NROI];      // cost-descending roi order

// ---------------- Fused prologue: tables + sort, one block ----------------
__global__ __launch_bounds__(NROI, 1)
void roi_prep_kernel(const float* __restrict__ rois) {
    __shared__ unsigned skey[NROI];

    int n = threadIdx.x;

    float x1 = rois[n*5+1] * SCALE_;
    float y1 = rois[n*5+2] * SCALE_;
    float x2 = rois[n*5+3] * SCALE_;
    float y2 = rois[n*5+4] * SCALE_;
    float cx = 0.5f*(x1+x2), cy = 0.5f*(y1+y2);
    float hw = 0.5f*(x2-x1), hh = 0.5f*(y2-y1);
    x1 = cx - hw; x2 = cx + hw;
    y1 = cy - hh; y2 = cy + hh;
    float roi_w = fmaxf(x2 - x1, 1.0f);
    float roi_h = fmaxf(y2 - y1, 1.0f);
    float bw = roi_w / (float)PW;
    float bh = roi_h / (float)PH;

    // ---- x table (serial per thread) ----
    // first sample to fix the even-aligned span start
    int x0e;
    {
        float sx = x1 + 0.5f * (bw * 0.5f);
        float c = fminf(fmaxf(sx, 0.0f), (float)(W_-1));
        x0e = ((int)floorf(c)) & ~1;
    }
    int jhi29 = 0;
    for (int i = 0; i < 32; i++) {
        XEnt e;
        if (i < SXG) {
            float sx = x1 + ((float)i + 0.5f) * (bw * 0.5f);
            bool valid = (sx > -1.0f) && (sx < (float)W_);
            float c = fminf(fmaxf(sx, 0.0f), (float)(W_-1));
            float lo = floorf(c);
            int ilo = (int)lo;
            int ihi = min(ilo + 1, W_-1);
            float fr = c - lo;
            float v = valid ? (1.0f/16.0f) : 0.0f;   // fold the final 1/16 here
            e.jlo = ilo - x0e; e.jhi = ihi - x0e;
            e.w0 = v*(1.0f-fr); e.w1 = v*fr;
            if (i == 29) jhi29 = ihi - x0e;
        } else {
            e.jlo = 0; e.jhi = 0; e.w0 = 0.0f; e.w1 = 0.0f;
        }
        g_x[n][i] = e;
    }
    int span2 = (jhi29 >> 1) + 1;
    int nw2 = ((span2 - 1) >> 5) + 1;
    nw2 = max(1, min(nw2, 2));
    int boff = (int)rois[n*5+0] * (C_ * HW_);
    g_hdr[n] = make_int4(x0e, nw2, boff, span2 - 1);

    // ---- y row-fold table ----
    int rowsMax = 2;
    for (int k = 0; k < PH; k++) {
        int rr[4]; float ww[4]; int m = 0;
        for (int j = 0; j < 2; j++) {
            int iy = 2*k + j;
            float sy = y1 + ((float)iy + 0.5f) * (bh * 0.5f);
            bool valid = (sy > -1.0f) && (sy < (float)H_);
            float c = fminf(fmaxf(sy, 0.0f), (float)(H_-1));
            float lo = floorf(c);
            int ilo = (int)lo;
            int ihi = min(ilo + 1, H_-1);
            float fr = c - lo;
            float v = valid ? 1.0f : 0.0f;
            float w0 = v*(1.0f-fr), w1 = v*fr;
            int r0 = ilo * W_, r1 = ihi * W_;

            if (w0 != 0.0f) {
                bool done = false;
                for (int q = 0; q < m; q++) if (rr[q] == r0) { ww[q] += w0; done = true; break; }
                if (!done) { rr[m] = r0; ww[m] = w0; m++; }
            }
            if (w1 != 0.0f) {
                bool done = false;
                for (int q = 0; q < m; q++) if (rr[q] == r1) { ww[q] += w1; done = true; break; }
                if (!done) { rr[m] = r1; ww[m] = w1; m++; }
            }
        }
        if (m == 0) { rr[0] = 0; ww[0] = 0.0f; m = 1; }
        int cnt = max(m, 2);
        rowsMax = max(rowsMax, cnt);
        for (int q = m; q < 4; q++) { rr[q] = rr[0]; ww[q] = 0.0f; }

        RW rw;
        #pragma unroll
        for (int q = 0; q < 4; q++) { rw.r[q] = rr[q]; rw.w[q] = ww[q]; }
        g_rw[n][k] = rw;
    }
    g_rows[n] = rowsMax;

    // ---- cost-descending bitonic sort ----
    int cost = rowsMax * nw2;    // 2..8
    unsigned key = ((unsigned)cost << 20) | (((unsigned)(span2-1) & 0xFFF) << 8) | (unsigned)n;
    skey[n] = key;
    __syncthreads();

    int t = n;
    for (int k = 2; k <= NROI; k <<= 1) {
        for (int j = k >> 1; j > 0; j >>= 1) {
            int ixj = t ^ j;
            if (ixj > t) {
                unsigned a = skey[t], b = skey[ixj];
                bool seg = ((t & k) == 0);
                if (seg ? (a < b) : (a > b)) { skey[t] = b; skey[ixj] = a; }
            }
            __syncthreads();
        }
    }
    g_perm[t] = (int)(skey[t] & 0xFFu);
}

// ---------------- Kernel B (identical to R12 hot loop, minus the 1/16) ----------------

template<int NW2>
__device__ __forceinline__ float gath(float2 P0, float2 P1,
                                      int le, int lo_, int ew, int ow,
                                      int c0, int c1, float wx0, float wx1)
{
    float ex, oy;
    if (NW2 == 1) {
        ex = __shfl_sync(FULLMASK, P0.x, le);
        oy = __shfl_sync(FULLMASK, P0.y, lo_);
    } else {
        float a0 = __shfl_sync(FULLMASK, P0.x, le);
        float a1 = __shfl_sync(FULLMASK, P1.x, le);
        ex = ew ? a1 : a0;
        float b0 = __shfl_sync(FULLMASK, P0.y, lo_);
        float b1 = __shfl_sync(FULLMASK, P1.y, lo_);
        oy = ow ? b1 : b0;
    }
    float g0 = c0 ? oy : ex;
    float g1 = c1 ? oy : ex;
    return wx0*g0 + wx1*g1;
}

template<int NW2, int ROWS>
__device__ __forceinline__ void pair_proc(
    const float* __restrict__ pu, const float* __restrict__ pv,
    const RW* __restrict__ srw,
    int lane, int xs2, int c0, int c1, int le, int lo_, int ew, int ow,
    float wx0, float wx1,
    float* __restrict__ ou, float* __restrict__ ov)
{
    bool emit = ((lane & 1) == 0) && (lane < 28);
    int lofs = lane >> 1;

    int j0 = min(lane, xs2);
    int j1 = min(lane + 32, xs2);

    float sPu = 0.0f, sPv = 0.0f;

    #pragma unroll 3
    for (int k = 0; k < 15; k++) {
        RW rw = srw[k];
        float2 Pu0 = make_float2(0.f,0.f), Pu1 = make_float2(0.f,0.f);
        float2 Pv0 = make_float2(0.f,0.f), Pv1 = make_float2(0.f,0.f);

        float2 au[ROWS], bu[ROWS], a1u[ROWS], b1u[ROWS];
        #pragma unroll
        for (int q = 0; q < ROWS; q++) {
            const float2* qu = (const float2*)(pu + rw.r[q]);
            const float2* qv = (const float2*)(pv + rw.r[q]);
            au[q] = __ldg(qu + j0);
            bu[q] = __ldg(qv + j0);
            if (NW2 > 1) {
                a1u[q] = __ldg(qu + j1);
                b1u[q] = __ldg(qv + j1);
            }
        }
        #pragma unroll
        for (int q = 0; q < ROWS; q++) {
            float w = rw.w[q];
            Pu0.x += w * au[q].x;  Pu0.y += w * au[q].y;
            Pv0.x += w * bu[q].x;  Pv0.y += w * bu[q].y;
            if (NW2 > 1) {
                Pu1.x += w * a1u[q].x;  Pu1.y += w * a1u[q].y;
                Pv1.x += w * b1u[q].x;  Pv1.y += w * b1u[q].y;
            }
        }

        float su = gath<NW2>(Pu0, Pu1, le, lo_, ew, ow, c0, c1, wx0, wx1);
        float sv = gath<NW2>(Pv0, Pv1, le, lo_, ew, ow, c0, c1, wx0, wx1);

        if (k) {
            float eu = sPu + su;
            float ev = sPv + sv;
            float tu = eu + __shfl_down_sync(FULLMASK, eu, 1);
            tu += __shfl_down_sync(FULLMASK, tu, 2);
            float tv = ev + __shfl_down_sync(FULLMASK, ev, 1);
            tv += __shfl_down_sync(FULLMASK, tv, 2);
            if (emit) {
                int idx = (k - 1) * OW + lofs;
                ou[idx] = tu;        // 1/16 folded into wx
                ov[idx] = tv;
            }
        }
        sPu = su;
        sPv = sv;
    }
}

__global__ __launch_bounds__(256, 6)
void roi_align_kernel(const float* __restrict__ feat, float* __restrict__ out) {
    __shared__ RW srw[PH];

    int n  = g_perm[blockIdx.x];
    int cg = blockIdx.y;          // 0..15, 16 channels per block
    int tid = threadIdx.x;
    int wid = tid >> 5, lane = tid & 31;

    if (tid < 2 * PH) {
        ((int4*)srw)[tid] = ((const int4*)g_rw[n])[tid];
    }
    __syncthreads();

    int4 hdr = g_hdr[n];
    int x0e = hdr.x, nw2 = hdr.y, boff = hdr.z, xs2 = hdr.w;
    int rows = g_rows[n];

    XEnt xe = g_x[n][lane];
    int c0 = xe.jlo & 1;
    int c1 = xe.jhi & 1;
    int je = c0 ? xe.jhi : xe.jlo;   // the even-column tap
    int jo = c0 ? xe.jlo : xe.jhi;   // the odd-column tap
    int le = (je >> 1) & 31, ew = je >> 6;
    int lo_ = (jo >> 1) & 31, ow = jo >> 6;
    float wx0 = xe.w0, wx1 = xe.w1;

    int c = cg * 16 + wid * 2;       // each warp: one channel pair
    const float* pu = feat + boff + x0e + c * HW_;
    const float* pv = pu + HW_;
    float* ou = out + (size_t)(n * C_ + c) * (OH * OW);
    float* ov = ou + OH * OW;

    if (nw2 == 1) {
        if (rows == 2)
            pair_proc<1,2>(pu, pv, srw, lane, xs2, c0, c1, le, lo_, ew, ow, wx0, wx1, ou, ov);
        else if (rows == 3)
            pair_proc<1,3>(pu, pv, srw, lane, xs2, c0, c1, le, lo_, ew, ow, wx0, wx1, ou, ov);
        else
            pair_proc<1,4>(pu, pv, srw, lane, xs2, c0, c1, le, lo_, ew, ow, wx0, wx1, ou, ov);
    } else {
        if (rows == 2)
            pair_proc<2,2>(pu, pv, srw, lane, xs2, c0, c1, le, lo_, ew, ow, wx0, wx1, ou, ov);
        else if (rows == 3)
            pair_proc<2,3>(pu, pv, srw, lane, xs2, c0, c1, le, lo_, ew, ow, wx0, wx1, ou, ov);
        else
            pair_proc<2,4>(pu, pv, srw, lane, xs2, c0, c1, le, lo_, ew, ow, wx0, wx1, ou, ov);
    }
}

extern "C" void kernel_launch(void* const* d_in, const int* in_sizes, int n_in,
                              void* d_out, int out_size) {
    const float* feat = (const float*)d_in[0];
    const float* rois = (const float*)d_in[1];
    float* out = (float*)d_out;

    roi_prep_kernel<<<1, NROI>>>(rois);
    dim3 grid(NROI, 16);
    roi_align_kernel<<<grid, 256>>>(feat, out);
}

// round 15
// speedup vs baseline: 1.2469x; 1.1760x over previous
#include <cuda_runtime.h>
#include <cuda_bf16.h>

// Problem constants (fixed by reference setup_inputs)
#define BATCH 2
#define C_    256
#define H_    200
#define W_    272
#define HW_   (H_*W_)
#define NROI  256
#define PH    15
#define PW    15
#define SXG   30
#define SYG   30
#define OH    14
#define OW    14
#define SCALE_ 0.25f

#define FULLMASK 0xFFFFFFFFu

struct XEnt { int jlo; int jhi; float w0; float w1; };       // relative to x0e, w pre-scaled by 1/16
struct alignas(16) RW { int r[4]; float w[4]; };             // folded distinct rows per k

__device__ XEnt g_x[NROI][32];
__device__ RW   g_rw[NROI][PH];
__device__ int4 g_hdr[NROI];       // {x0e, nw2, boff, span2-1}
__device__ int  g_rows[NROI];      // max distinct rows over k (2..4)
__device__ int  g_perm[NROI];      // cost-descending roi order

// ---------------- Kernel A: per-roi tables (parallel) ----------------
__global__ void roi_tab_kernel(const float* __restrict__ rois) {
    int n = blockIdx.x;
    int t = threadIdx.x;   // 64 threads

    float x1 = rois[n*5+1] * SCALE_;
    float y1 = rois[n*5+2] * SCALE_;
    float x2 = rois[n*5+3] * SCALE_;
    float y2 = rois[n*5+4] * SCALE_;
    float cx = 0.5f*(x1+x2), cy = 0.5f*(y1+y2);
    float hw = 0.5f*(x2-x1), hh = 0.5f*(y2-y1);
    x1 = cx - hw; x2 = cx + hw;
    y1 = cy - hh; y2 = cy + hh;
    float roi_w = fmaxf(x2 - x1, 1.0f);
    float roi_h = fmaxf(y2 - y1, 1.0f);
    float bw = roi_w / (float)PW;
    float bh = roi_h / (float)PH;

    if (t < 32) {
        int i = t;
        float sx = x1 + ((float)i + 0.5f) * (bw * 0.5f);
        bool valid = (sx > -1.0f) && (sx < (float)W_);
        float c = fminf(fmaxf(sx, 0.0f), (float)(W_-1));
        float lo = floorf(c);
        int ilo = (int)lo;
        int ihi = min(ilo + 1, W_-1);
        float fr = c - lo;
        float v = valid ? (1.0f/16.0f) : 0.0f;      // fold final 1/16 here

        int x0e = __shfl_sync(FULLMASK, ilo, 0) & ~1;   // even-aligned span start
        int jhi29 = __shfl_sync(FULLMASK, ihi, 29) - x0e;

        XEnt e;
        if (i < SXG) { e.jlo = ilo - x0e; e.jhi = ihi - x0e; e.w0 = v*(1.0f-fr); e.w1 = v*fr; }
        else         { e.jlo = 0; e.jhi = 0; e.w0 = 0.0f; e.w1 = 0.0f; }
        g_x[n][i] = e;

        if (i == 0) {
            int span2 = (jhi29 >> 1) + 1;          // float2 words needed
            int nw2 = ((span2 - 1) >> 5) + 1;      // 1 or 2 warp-words
            nw2 = max(1, min(nw2, 2));
            int boff = (int)rois[n*5+0] * (C_ * HW_);
            g_hdr[n] = make_int4(x0e, nw2, boff, span2 - 1);
        }
    } else if (t < 48) {
        int k = t - 32;
        int cnt = 2;
        if (k < PH) {
            int rr[4]; float ww[4]; int m = 0;

            #pragma unroll
            for (int j = 0; j < 2; j++) {
                int iy = 2*k + j;
                float sy = y1 + ((float)iy + 0.5f) * (bh * 0.5f);
                bool valid = (sy > -1.0f) && (sy < (float)H_);
                float c = fminf(fmaxf(sy, 0.0f), (float)(H_-1));
                float lo = floorf(c);
                int ilo = (int)lo;
                int ihi = min(ilo + 1, H_-1);
                float fr = c - lo;
                float v = valid ? 1.0f : 0.0f;
                float w0 = v*(1.0f-fr), w1 = v*fr;
                int r0 = ilo * W_, r1 = ihi * W_;

                if (w0 != 0.0f) {
                    bool done = false;
                    for (int q = 0; q < m; q++) if (rr[q] == r0) { ww[q] += w0; done = true; break; }
                    if (!done) { rr[m] = r0; ww[m] = w0; m++; }
                }
                if (w1 != 0.0f) {
                    bool done = false;
                    for (int q = 0; q < m; q++) if (rr[q] == r1) { ww[q] += w1; done = true; break; }
                    if (!done) { rr[m] = r1; ww[m] = w1; m++; }
                }
            }
            if (m == 0) { rr[0] = 0; ww[0] = 0.0f; m = 1; }
            cnt = max(m, 2);
            for (int q = m; q < 4; q++) { rr[q] = rr[0]; ww[q] = 0.0f; }

            RW rw;
            #pragma unroll
            for (int q = 0; q < 4; q++) { rw.r[q] = rr[q]; rw.w[q] = ww[q]; }
            g_rw[n][k] = rw;
        }
        int mx = cnt;
        #pragma unroll
        for (int d = 8; d >= 1; d >>= 1)
            mx = max(mx, __shfl_xor_sync(0xFFFFu, mx, d));
        if (k == 0) g_rows[n] = mx;
    }
}

// ---------------- Kernel A2: cost-descending bitonic sort of rois ----------------
__global__ void roi_sort_kernel() {
    __shared__ unsigned skey[NROI];
    int t = threadIdx.x;

    int4 hdr = g_hdr[t];
    int cost = g_rows[t] * hdr.y;                 // 2..8
    unsigned key = ((unsigned)cost << 20) | (((unsigned)hdr.w & 0xFFF) << 8) | (unsigned)t;
    skey[t] = key;
    __syncthreads();

    for (int k = 2; k <= NROI; k <<= 1) {
        for (int j = k >> 1; j > 0; j >>= 1) {
            int ixj = t ^ j;
            if (ixj > t) {
                unsigned a = skey[t], b = skey[ixj];
                bool seg = ((t & k) == 0);
                if (seg ? (a < b) : (a > b)) { skey[t] = b; skey[ixj] = a; }
            }
            __syncthreads();
        }
    }
    g_perm[t] = (int)(skey[t] & 0xFFu);
}

// ---------------- Kernel B ----------------

template<int NW2>
__device__ __forceinline__ float gath(float2 P0, float2 P1,
                                      int le, int lo_, int ew, int ow,
                                      int c0, int c1, float wx0, float wx1)
{
    float ex, oy;
    if (NW2 == 1) {
        ex = __shfl_sync(FULLMASK, P0.x, le);
        oy = __shfl_sync(FULLMASK, P0.y, lo_);
    } else {
        float a0 = __shfl_sync(FULLMASK, P0.x, le);
        float a1 = __shfl_sync(FULLMASK, P1.x, le);
        ex = ew ? a1 : a0;
        float b0 = __shfl_sync(FULLMASK, P0.y, lo_);
        float b1 = __shfl_sync(FULLMASK, P1.y, lo_);
        oy = ow ? b1 : b0;
    }
    float g0 = c0 ? oy : ex;
    float g1 = c1 ? oy : ex;
    return wx0*g0 + wx1*g1;
}

template<int NW2, int ROWS>
__device__ __forceinline__ void pair_proc(
    const float* __restrict__ pu, const float* __restrict__ pv,
    const RW* __restrict__ srw,
    int lane, int xs2, int c0, int c1, int le, int lo_, int ew, int ow,
    float wx0, float wx1,
    float* __restrict__ ou, float* __restrict__ ov)
{
    bool emit = ((lane & 1) == 0) && (lane < 28);
    int lofs = lane >> 1;

    int j0 = min(lane, xs2);
    int j1 = min(lane + 32, xs2);

    float sPu = 0.0f, sPv = 0.0f;

    #pragma unroll 3
    for (int k = 0; k < 15; k++) {
        RW rw = srw[k];
        float2 Pu0 = make_float2(0.f,0.f), Pu1 = make_float2(0.f,0.f);
        float2 Pv0 = make_float2(0.f,0.f), Pv1 = make_float2(0.f,0.f);

        float2 au[ROWS], bu[ROWS], a1u[ROWS], b1u[ROWS];
        #pragma unroll
        for (int q = 0; q < ROWS; q++) {
            const float2* qu = (const float2*)(pu + rw.r[q]);
            const float2* qv = (const float2*)(pv + rw.r[q]);
            au[q] = __ldg(qu + j0);
            bu[q] = __ldg(qv + j0);
            if (NW2 > 1) {
                a1u[q] = __ldg(qu + j1);
                b1u[q] = __ldg(qv + j1);
            }
        }
        #pragma unroll
        for (int q = 0; q < ROWS; q++) {
            float w = rw.w[q];
            Pu0.x += w * au[q].x;  Pu0.y += w * au[q].y;
            Pv0.x += w * bu[q].x;  Pv0.y += w * bu[q].y;
            if (NW2 > 1) {
                Pu1.x += w * a1u[q].x;  Pu1.y += w * a1u[q].y;
                Pv1.x += w * b1u[q].x;  Pv1.y += w * b1u[q].y;
            }
        }

        float su = gath<NW2>(Pu0, Pu1, le, lo_, ew, ow, c0, c1, wx0, wx1);
        float sv = gath<NW2>(Pv0, Pv1, le, lo_, ew, ow, c0, c1, wx0, wx1);

        if (k) {
            float eu = sPu + su;
            float ev = sPv + sv;
            float tu = eu + __shfl_down_sync(FULLMASK, eu, 1);
            tu += __shfl_down_sync(FULLMASK, tu, 2);
            float tv = ev + __shfl_down_sync(FULLMASK, ev, 1);
            tv += __shfl_down_sync(FULLMASK, tv, 2);
            if (emit) {
                int idx = (k - 1) * OW + lofs;
                ou[idx] = tu;       // 1/16 folded into x-weights
                ov[idx] = tv;
            }
        }
        sPu = su;
        sPv = sv;
    }
}

template<int NW2, int ROWS>
__device__ __forceinline__ void run_variant(
    const float* base, float* out, const RW* srw, int n, int cbase,
    int lane, int xs2, int c0, int c1, int le, int lo_, int ew, int ow,
    float wx0, float wx1)
{
    #pragma unroll
    for (int p = 0; p < 2; p++) {
        int c = cbase + 2 * p;
        const float* pu = base + c * HW_;
        const float* pv = pu + HW_;
        float* ou = out + (size_t)(n * C_ + c) * (OH * OW);
        float* ov = ou + OH * OW;
        pair_proc<NW2, ROWS>(pu, pv, srw, lane, xs2, c0, c1, le, lo_, ew, ow, wx0, wx1, ou, ov);
    }
}

__global__ __launch_bounds__(256, 6)
void roi_align_kernel(const float* __restrict__ feat, float* __restrict__ out) {
    __shared__ RW srw[PH];

    int n  = g_perm[blockIdx.x];
    int cg = blockIdx.y;          // 0..7, 32 channels per block
    int tid = threadIdx.x;
    int wid = tid >> 5, lane = tid & 31;

    if (tid < 2 * PH) {
        ((int4*)srw)[tid] = ((const int4*)g_rw[n])[tid];
    }
    __syncthreads();

    int4 hdr = g_hdr[n];
    int x0e = hdr.x, nw2 = hdr.y, boff = hdr.z, xs2 = hdr.w;
    int rows = g_rows[n];

    XEnt xe = g_x[n][lane];
    int c0 = xe.jlo & 1;
    int c1 = xe.jhi & 1;
    int je = c0 ? xe.jhi : xe.jlo;   // the even-column tap
    int jo = c0 ? xe.jlo : xe.jhi;   // the odd-column tap
    int le = (je >> 1) & 31, ew = je >> 6;
    int lo_ = (jo >> 1) & 31, ow = jo >> 6;
    float wx0 = xe.w0, wx1 = xe.w1;

    const float* base = feat + boff + x0e;
    int cbase = cg * 32 + wid * 4;   // each warp: 4 channels (2 sequential pairs)

    if (nw2 == 1) {
        if (rows == 2)
            run_variant<1,2>(base, out, srw, n, cbase, lane, xs2, c0, c1, le, lo_, ew, ow, wx0, wx1);
        else if (rows == 3)
            run_variant<1,3>(base, out, srw, n, cbase, lane, xs2, c0, c1, le, lo_, ew, ow, wx0, wx1);
        else
            run_variant<1,4>(base, out, srw, n, cbase, lane, xs2, c0, c1, le, lo_, ew, ow, wx0, wx1);
    } else {
        if (rows == 2)
            run_variant<2,2>(base, out, srw, n, cbase, lane, xs2, c0, c1, le, lo_, ew, ow, wx0, wx1);
        else if (rows == 3)
            run_variant<2,3>(base, out, srw, n, cbase, lane, xs2, c0, c1, le, lo_, ew, ow, wx0, wx1);
        else
            run_variant<2,4>(base, out, srw, n, cbase, lane, xs2, c0, c1, le, lo_, ew, ow, wx0, wx1);
    }
}

extern "C" void kernel_launch(void* const* d_in, const int* in_sizes, int n_in,
                              void* d_out, int out_size) {
    const float* feat = (const float*)d_in[0];
    const float* rois = (const float*)d_in[1];
    float* out = (float*)d_out;

    roi_tab_kernel<<<NROI, 64>>>(rois);
    roi_sort_kernel<<<1, NROI>>>();
    dim3 grid(NROI, 8);
    roi_align_kernel<<<grid, 256>>>(feat, out);
}

// round 16
// speedup vs baseline: 1.4146x; 1.1345x over previous
#include <cuda_runtime.h>
#include <cuda_bf16.h>

// Problem constants (fixed by reference setup_inputs)
#define BATCH 2
#define C_    256
#define H_    200
#define W_    272
#define HW_   (H_*W_)
#define NROI  256
#define PH    15
#define PW    15
#define SXG   30
#define SYG   30
#define OH    14
#define OW    14
#define SCALE_ 0.25f

#define FULLMASK 0xFFFFFFFFu

struct XEnt { int jlo; int jhi; float w0; float w1; };       // relative to x0e, w pre-scaled by 1/16
struct alignas(16) RW { int r[4]; float w[4]; };             // folded distinct rows per k

__device__ XEnt g_x[NROI][32];
__device__ RW   g_rw[NROI][PH];
__device__ int4 g_hdr[NROI];       // {x0e, nw2, boff, span2-1}
__device__ int  g_rows[NROI];      // max distinct rows over k (2..4)
__device__ int  g_perm[NROI];      // cost-descending roi order

// ---------------- Kernel A: per-roi tables ----------------
__global__ void roi_tab_kernel(const float* __restrict__ rois) {
    int n = blockIdx.x;
    int t = threadIdx.x;   // 64 threads

    float x1 = rois[n*5+1] * SCALE_;
    float y1 = rois[n*5+2] * SCALE_;
    float x2 = rois[n*5+3] * SCALE_;
    float y2 = rois[n*5+4] * SCALE_;
    float cx = 0.5f*(x1+x2), cy = 0.5f*(y1+y2);
    float hw = 0.5f*(x2-x1), hh = 0.5f*(y2-y1);
    x1 = cx - hw; x2 = cx + hw;
    y1 = cy - hh; y2 = cy + hh;
    float roi_w = fmaxf(x2 - x1, 1.0f);
    float roi_h = fmaxf(y2 - y1, 1.0f);
    float bw = roi_w / (float)PW;
    float bh = roi_h / (float)PH;

    if (t < 32) {
        int i = t;
        float sx = x1 + ((float)i + 0.5f) * (bw * 0.5f);
        bool valid = (sx > -1.0f) && (sx < (float)W_);
        float c = fminf(fmaxf(sx, 0.0f), (float)(W_-1));
        float lo = floorf(c);
        int ilo = (int)lo;
        int ihi = min(ilo + 1, W_-1);
        float fr = c - lo;
        float v = valid ? (1.0f/16.0f) : 0.0f;      // fold the final 1/16 here

        int x0e = __shfl_sync(FULLMASK, ilo, 0) & ~1;   // even-aligned span start
        int jhi29 = __shfl_sync(FULLMASK, ihi, 29) - x0e;

        XEnt e;
        if (i < SXG) { e.jlo = ilo - x0e; e.jhi = ihi - x0e; e.w0 = v*(1.0f-fr); e.w1 = v*fr; }
        else         { e.jlo = 0; e.jhi = 0; e.w0 = 0.0f; e.w1 = 0.0f; }
        g_x[n][i] = e;

        if (i == 0) {
            int span2 = (jhi29 >> 1) + 1;          // float2 words needed
            int nw2 = ((span2 - 1) >> 5) + 1;      // 1 or 2 warp-words
            nw2 = max(1, min(nw2, 2));
            int boff = (int)rois[n*5+0] * (C_ * HW_);
            g_hdr[n] = make_int4(x0e, nw2, boff, span2 - 1);
        }
    } else if (t < 48) {
        int k = t - 32;
        int cnt = 2;
        if (k < PH) {
            int rr[4]; float ww[4]; int m = 0;

            #pragma unroll
            for (int j = 0; j < 2; j++) {
                int iy = 2*k + j;
                float sy = y1 + ((float)iy + 0.5f) * (bh * 0.5f);
                bool valid = (sy > -1.0f) && (sy < (float)H_);
                float c = fminf(fmaxf(sy, 0.0f), (float)(H_-1));
                float lo = floorf(c);
                int ilo = (int)lo;
                int ihi = min(ilo + 1, H_-1);
                float fr = c - lo;
                float v = valid ? 1.0f : 0.0f;
                float w0 = v*(1.0f-fr), w1 = v*fr;
                int r0 = ilo * W_, r1 = ihi * W_;

                if (w0 != 0.0f) {
                    bool done = false;
                    for (int q = 0; q < m; q++) if (rr[q] == r0) { ww[q] += w0; done = true; break; }
                    if (!done) { rr[m] = r0; ww[m] = w0; m++; }
                }
                if (w1 != 0.0f) {
                    bool done = false;
                    for (int q = 0; q < m; q++) if (rr[q] == r1) { ww[q] += w1; done = true; break; }
                    if (!done) { rr[m] = r1; ww[m] = w1; m++; }
                }
            }
            if (m == 0) { rr[0] = 0; ww[0] = 0.0f; m = 1; }
            cnt = max(m, 2);
            for (int q = m; q < 4; q++) { rr[q] = rr[0]; ww[q] = 0.0f; }

            RW rw;
            #pragma unroll
            for (int q = 0; q < 4; q++) { rw.r[q] = rr[q]; rw.w[q] = ww[q]; }
            g_rw[n][k] = rw;
        }
        // max over the 16 lanes of this group (lane ids 0..15 of warp 1)
        int mx = cnt;
        #pragma unroll
        for (int d = 8; d >= 1; d >>= 1)
            mx = max(mx, __shfl_xor_sync(0xFFFFu, mx, d));
        if (k == 0) g_rows[n] = mx;
    }
}

// ---------------- Kernel A2: cost-descending bitonic sort of rois ----------------
__global__ void roi_sort_kernel() {
    __shared__ unsigned skey[NROI];
    int t = threadIdx.x;

    int4 hdr = g_hdr[t];
    int cost = g_rows[t] * hdr.y;                 // 2..8
    // key: cost (hi) | span (mid) | idx (lo 8 bits)
    unsigned key = ((unsigned)cost << 20) | (((unsigned)hdr.w & 0xFFF) << 8) | (unsigned)t;
    skey[t] = key;
    __syncthreads();

    for (int k = 2; k <= NROI; k <<= 1) {
        for (int j = k >> 1; j > 0; j >>= 1) {
            int ixj = t ^ j;
            if (ixj > t) {
                unsigned a = skey[t], b = skey[ixj];
                bool seg = ((t & k) == 0);
                // descending sort: in 'seg' segments keep larger first
                if (seg ? (a < b) : (a > b)) { skey[t] = b; skey[ixj] = a; }
            }
            __syncthreads();
        }
    }
    g_perm[t] = (int)(skey[t] & 0xFFu);
}

// ---------------- Kernel B ----------------

// Horizontal gather of the two x-taps from the accumulated pair-sum.
template<int NW2>
__device__ __forceinline__ float gath(float2 P0, float2 P1,
                                      int le, int lo_, int ew, int ow,
                                      int c0, int c1, float wx0, float wx1)
{
    float ex, oy;
    if (NW2 == 1) {
        ex = __shfl_sync(FULLMASK, P0.x, le);
        oy = __shfl_sync(FULLMASK, P0.y, lo_);
    } else {
        float a0 = __shfl_sync(FULLMASK, P0.x, le);
        float a1 = __shfl_sync(FULLMASK, P1.x, le);
        ex = ew ? a1 : a0;
        float b0 = __shfl_sync(FULLMASK, P0.y, lo_);
        float b1 = __shfl_sync(FULLMASK, P1.y, lo_);
        oy = ow ? b1 : b0;
    }
    float g0 = c0 ? oy : ex;
    float g1 = c1 ? oy : ex;
    return wx0*g0 + wx1*g1;
}

template<int NW2, int ROWS>
__device__ __forceinline__ void pair_proc(
    const float* __restrict__ pu, const float* __restrict__ pv,
    const RW* __restrict__ srw,
    int lane, int xs2, int c0, int c1, int le, int lo_, int ew, int ow,
    float wx0, float wx1,
    float* __restrict__ ou, float* __restrict__ ov)
{
    bool emit = ((lane & 1) == 0) && (lane < 28);
    int lofs = lane >> 1;

    int j0 = min(lane, xs2);
    int j1 = min(lane + 32, xs2);   // collapses onto last needed line

    float sPu = 0.0f, sPv = 0.0f;

    #pragma unroll 3
    for (int k = 0; k < 15; k++) {
        RW rw = srw[k];
        float2 Pu0 = make_float2(0.f,0.f), Pu1 = make_float2(0.f,0.f);
        float2 Pv0 = make_float2(0.f,0.f), Pv1 = make_float2(0.f,0.f);

        float2 au[ROWS], bu[ROWS], a1u[ROWS], b1u[ROWS];
        #pragma unroll
        for (int q = 0; q < ROWS; q++) {
            const float2* qu = (const float2*)(pu + rw.r[q]);
            const float2* qv = (const float2*)(pv + rw.r[q]);
            au[q] = __ldg(qu + j0);
            bu[q] = __ldg(qv + j0);
            if (NW2 > 1) {
                a1u[q] = __ldg(qu + j1);
                b1u[q] = __ldg(qv + j1);
            }
        }
        #pragma unroll
        for (int q = 0; q < ROWS; q++) {
            float w = rw.w[q];
            Pu0.x += w * au[q].x;  Pu0.y += w * au[q].y;
            Pv0.x += w * bu[q].x;  Pv0.y += w * bu[q].y;
            if (NW2 > 1) {
                Pu1.x += w * a1u[q].x;  Pu1.y += w * a1u[q].y;
                Pv1.x += w * b1u[q].x;  Pv1.y += w * b1u[q].y;
            }
        }

        float su = gath<NW2>(Pu0, Pu1, le, lo_, ew, ow, c0, c1, wx0, wx1);
        float sv = gath<NW2>(Pv0, Pv1, le, lo_, ew, ow, c0, c1, wx0, wx1);

        if (k) {
            float eu = sPu + su;
            float ev = sPv + sv;
            float tu = eu + __shfl_down_sync(FULLMASK, eu, 1);
            tu += __shfl_down_sync(FULLMASK, tu, 2);
            float tv = ev + __shfl_down_sync(FULLMASK, ev, 1);
            tv += __shfl_down_sync(FULLMASK, tv, 2);
            if (emit) {
                int idx = (k - 1) * OW + lofs;
                ou[idx] = tu;        // 1/16 pre-folded into x-weights
                ov[idx] = tv;
            }
        }
        sPu = su;
        sPv = sv;
    }
}

__global__ __launch_bounds__(256, 6)
void roi_align_kernel(const float* __restrict__ feat, float* __restrict__ out) {
    __shared__ RW srw[PH];

    int n  = g_perm[blockIdx.x];
    int cg = blockIdx.y;          // 0..15, 16 channels per block
    int tid = threadIdx.x;
    int wid = tid >> 5, lane = tid & 31;

    if (tid < 2 * PH) {
        ((int4*)srw)[tid] = ((const int4*)g_rw[n])[tid];
    }
    __syncthreads();

    int4 hdr = g_hdr[n];
    int x0e = hdr.x, nw2 = hdr.y, boff = hdr.z, xs2 = hdr.w;
    int rows = g_rows[n];

    XEnt xe = g_x[n][lane];
    int c0 = xe.jlo & 1;
    int c1 = xe.jhi & 1;
    int je = c0 ? xe.jhi : xe.jlo;   // the even-column tap
    int jo = c0 ? xe.jlo : xe.jhi;   // the odd-column tap
    int le = (je >> 1) & 31, ew = je >> 6;
    int lo_ = (jo >> 1) & 31, ow = jo >> 6;
    float wx0 = xe.w0, wx1 = xe.w1;

    int c = cg * 16 + wid * 2;       // each warp: one channel pair
    const float* pu = feat + boff + x0e + c * HW_;
    const float* pv = pu + HW_;
    float* ou = out + (size_t)(n * C_ + c) * (OH * OW);
    float* ov = ou + OH * OW;

    if (nw2 == 1) {
        if (rows == 2)
            pair_proc<1,2>(pu, pv, srw, lane, xs2, c0, c1, le, lo_, ew, ow, wx0, wx1, ou, ov);
        else if (rows == 3)
            pair_proc<1,3>(pu, pv, srw, lane, xs2, c0, c1, le, lo_, ew, ow, wx0, wx1, ou, ov);
        else
            pair_proc<1,4>(pu, pv, srw, lane, xs2, c0, c1, le, lo_, ew, ow, wx0, wx1, ou, ov);
    } else {
        if (rows == 2)
            pair_proc<2,2>(pu, pv, srw, lane, xs2, c0, c1, le, lo_, ew, ow, wx0, wx1, ou, ov);
        else if (rows == 3)
            pair_proc<2,3>(pu, pv, srw, lane, xs2, c0, c1, le, lo_, ew, ow, wx0, wx1, ou, ov);
        else
            pair_proc<2,4>(pu, pv, srw, lane, xs2, c0, c1, le, lo_, ew, ow, wx0, wx1, ou, ov);
    }
}

extern "C" void kernel_launch(void* const* d_in, const int* in_sizes, int n_in,
                              void* d_out, int out_size) {
    const float* feat = (const float*)d_in[0];
    const float* rois = (const float*)d_in[1];
    float* out = (float*)d_out;

    roi_tab_kernel<<<NROI, 64>>>(rois);
    roi_sort_kernel<<<1, NROI>>>();
    dim3 grid(NROI, 16);
    roi_align_kernel<<<grid, 256>>>(feat, out);
}